// round 15
// baseline (speedup 1.0000x reference)
#include <cuda_runtime.h>
#include <cuda_fp16.h>
#include <cstdint>

// CuGraphSAGEConv pipeline — R14 kernels + chunked gather/gemm overlap:
//   K0 convert: x(f32) -> g_xh(fp16); W(f32) -> g_wh fp16   [main stream]
//   K1 gather (x4 chunks, serial, main stream)
//   K2 gemm   (x4 chunks on side stream, each gated on its gather chunk,
//              overlapping the NEXT gather chunk)

#define D_IN  64
#define DK    128
#define D_OUT 64

#define NPAD    100352
#define NCHUNK  25088          // nodes per chunk (4 chunks; 196 tiles each)
#define TCHUNK  196

__device__ unsigned char g_agg[(size_t)NPAD * 128];   // fp16 agg row (128B)
__device__ __half        g_xh[(size_t)NPAD * D_IN];   // fp16 x row (128B)
__device__ unsigned char g_wh[64 * 256];              // fp16 W row (256B)

// ======================= helpers =======================
__device__ __forceinline__ uint32_t smem_u32(const void* p) {
    uint32_t a;
    asm("{ .reg .u64 t; cvta.to.shared.u64 t, %1; cvt.u32.u64 %0, t; }"
        : "=r"(a) : "l"(p));
    return a;
}
__device__ __forceinline__ void ldm_x4(uint4& r, uint32_t addr) {
    asm volatile("ldmatrix.sync.aligned.m8n8.x4.shared.b16 {%0,%1,%2,%3}, [%4];"
                 : "=r"(r.x), "=r"(r.y), "=r"(r.z), "=r"(r.w) : "r"(addr));
}
__device__ __forceinline__ void mma16816h(float* c, const uint4& a,
                                          uint32_t b0, uint32_t b1) {
    asm volatile(
        "mma.sync.aligned.m16n8k16.row.col.f32.f16.f16.f32 "
        "{%0,%1,%2,%3}, {%4,%5,%6,%7}, {%8,%9}, {%0,%1,%2,%3};"
        : "+f"(c[0]), "+f"(c[1]), "+f"(c[2]), "+f"(c[3])
        : "r"(a.x), "r"(a.y), "r"(a.z), "r"(a.w), "r"(b0), "r"(b1));
}
__device__ __forceinline__ void cp16(uint32_t dst, const void* src) {
    asm volatile("cp.async.cg.shared.global [%0], [%1], 16;"
                 :: "r"(dst), "l"(src));
}
__device__ __forceinline__ __half2 u2h(uint32_t u) {
    return *reinterpret_cast<__half2*>(&u);
}
__device__ __forceinline__ void tree4(float* acc, const uint4& v0, const uint4& v1,
                                      const uint4& v2, const uint4& v3) {
    __half2 s0 = __hadd2(__hadd2(u2h(v0.x), u2h(v1.x)), __hadd2(u2h(v2.x), u2h(v3.x)));
    __half2 s1 = __hadd2(__hadd2(u2h(v0.y), u2h(v1.y)), __hadd2(u2h(v2.y), u2h(v3.y)));
    __half2 s2 = __hadd2(__hadd2(u2h(v0.z), u2h(v1.z)), __hadd2(u2h(v2.z), u2h(v3.z)));
    __half2 s3 = __hadd2(__hadd2(u2h(v0.w), u2h(v1.w)), __hadd2(u2h(v2.w), u2h(v3.w)));
    float2 f;
    f = __half22float2(s0); acc[0] += f.x; acc[1] += f.y;
    f = __half22float2(s1); acc[2] += f.x; acc[3] += f.y;
    f = __half22float2(s2); acc[4] += f.x; acc[5] += f.y;
    f = __half22float2(s3); acc[6] += f.x; acc[7] += f.y;
}

// ======================= K0: convert x and W =======================
#define XCBLK 1568   // x blocks: 1568*256*4 >= 1.6M float4

__global__ __launch_bounds__(256)
void convert_kernel(const float4* __restrict__ x4,
                    const float4* __restrict__ W4, int nx)
{
    const int tid = threadIdx.x;
    if (blockIdx.x >= XCBLK) {
        const int c = (blockIdx.x - XCBLK) * 256 + tid;   // 0..1023
        const int o = c >> 4;
        const int q = c & 15;
        float4 v0 = __ldg(W4 + o * 32 + q * 2);
        float4 v1 = __ldg(W4 + o * 32 + q * 2 + 1);
        __half2 h0 = __floats2half2_rn(v0.x, v0.y);
        __half2 h1 = __floats2half2_rn(v0.z, v0.w);
        __half2 h2 = __floats2half2_rn(v1.x, v1.y);
        __half2 h3 = __floats2half2_rn(v1.z, v1.w);
        uint4 p = make_uint4(*reinterpret_cast<uint32_t*>(&h0),
                             *reinterpret_cast<uint32_t*>(&h1),
                             *reinterpret_cast<uint32_t*>(&h2),
                             *reinterpret_cast<uint32_t*>(&h3));
        *reinterpret_cast<uint4*>(g_wh + (size_t)o * 256 + q * 16) = p;
        return;
    }
    const int stride = XCBLK * 256;
    const int i0 = blockIdx.x * 256 + tid;
    #pragma unroll
    for (int j = 0; j < 4; j++) {
        const int i = i0 + j * stride;
        if (i < nx) {
            float4 v = __ldg(x4 + i);
            __half2 h01 = __floats2half2_rn(v.x, v.y);
            __half2 h23 = __floats2half2_rn(v.z, v.w);
            uint2 hp;
            hp.x = *reinterpret_cast<uint32_t*>(&h01);
            hp.y = *reinterpret_cast<uint32_t*>(&h23);
            reinterpret_cast<uint2*>(g_xh)[i] = hp;
        }
    }
}

// ======================= K1: gather (node range) =======================
__global__ __launch_bounds__(256)
void gather_kernel(const int* __restrict__ row,
                   const int* __restrict__ colptr,
                   int n_lo, int n_hi)
{
    const int g  = n_lo + ((blockIdx.x * 256 + threadIdx.x) >> 3);
    const int gl = threadIdx.x & 7;
    if (g >= n_hi) return;

    const uint4* xh4 = reinterpret_cast<const uint4*>(g_xh);

    const int e0 = __ldg(colptr + g);
    const int e1 = __ldg(colptr + g + 1);

    float acc[8];
    #pragma unroll
    for (int i = 0; i < 8; i++) acc[i] = 0.f;

    int e = e0;
    if (e + 8 <= e1) {
        int s[8];
        #pragma unroll
        for (int j = 0; j < 8; j++) s[j] = __ldg(row + e + j);
        e += 8;
        while (true) {
            const bool more = (e + 8 <= e1);
            int t[8];
            if (more) {
                #pragma unroll
                for (int j = 0; j < 8; j++) t[j] = __ldg(row + e + j);
            }
            uint4 v0 = __ldg(xh4 + (size_t)s[0] * 8 + gl);
            uint4 v1 = __ldg(xh4 + (size_t)s[1] * 8 + gl);
            uint4 v2 = __ldg(xh4 + (size_t)s[2] * 8 + gl);
            uint4 v3 = __ldg(xh4 + (size_t)s[3] * 8 + gl);
            uint4 v4 = __ldg(xh4 + (size_t)s[4] * 8 + gl);
            uint4 v5 = __ldg(xh4 + (size_t)s[5] * 8 + gl);
            uint4 v6 = __ldg(xh4 + (size_t)s[6] * 8 + gl);
            uint4 v7 = __ldg(xh4 + (size_t)s[7] * 8 + gl);
            tree4(acc, v0, v1, v2, v3);
            tree4(acc, v4, v5, v6, v7);
            if (!more) break;
            #pragma unroll
            for (int j = 0; j < 8; j++) s[j] = t[j];
            e += 8;
        }
    }
    if (e + 4 <= e1) {
        int s0 = __ldg(row + e), s1 = __ldg(row + e + 1);
        int s2 = __ldg(row + e + 2), s3 = __ldg(row + e + 3);
        uint4 v0 = __ldg(xh4 + (size_t)s0 * 8 + gl);
        uint4 v1 = __ldg(xh4 + (size_t)s1 * 8 + gl);
        uint4 v2 = __ldg(xh4 + (size_t)s2 * 8 + gl);
        uint4 v3 = __ldg(xh4 + (size_t)s3 * 8 + gl);
        tree4(acc, v0, v1, v2, v3);
        e += 4;
    }
    for (; e < e1; e++) {
        int s = __ldg(row + e);
        uint4 v = __ldg(xh4 + (size_t)s * 8 + gl);
        float2 f;
        f = __half22float2(u2h(v.x)); acc[0] += f.x; acc[1] += f.y;
        f = __half22float2(u2h(v.y)); acc[2] += f.x; acc[3] += f.y;
        f = __half22float2(u2h(v.z)); acc[4] += f.x; acc[5] += f.y;
        f = __half22float2(u2h(v.w)); acc[6] += f.x; acc[7] += f.y;
    }

    const int deg = e1 - e0;
    const float inv = 1.f / (float)(deg > 0 ? deg : 1);
    #pragma unroll
    for (int i = 0; i < 8; i++) acc[i] *= inv;

    __half2 h0 = __floats2half2_rn(acc[0], acc[1]);
    __half2 h1 = __floats2half2_rn(acc[2], acc[3]);
    __half2 h2 = __floats2half2_rn(acc[4], acc[5]);
    __half2 h3 = __floats2half2_rn(acc[6], acc[7]);
    uint4 o4 = make_uint4(*reinterpret_cast<uint32_t*>(&h0),
                          *reinterpret_cast<uint32_t*>(&h1),
                          *reinterpret_cast<uint32_t*>(&h2),
                          *reinterpret_cast<uint32_t*>(&h3));
    *reinterpret_cast<uint4*>(g_agg + (size_t)g * 128 + gl * 16) = o4;
}

// ======================= K2: pipelined HMMA GEMM (tile range) =======================
#define TB     128
#define ROWB   272
#define SM_WHI 0
#define SM_A0  17408
#define SM_A1  52224
#define SM_TOT 87040
#define GRIDC  98        // blocks per gemm chunk (2 tiles each)

extern __shared__ char g_sm[];

__device__ __forceinline__ void stage_tile(uint32_t sb, int buf, int tbase, int tid)
{
    const uint32_t abase = sb + (buf ? SM_A1 : SM_A0);
    #pragma unroll
    for (int j = 0; j < 8; j++) {
        const int c = tid + 256 * j;
        const int r = c >> 4;
        const int q = c & 15;
        const unsigned char* src = (q < 8)
            ? g_agg + (size_t)(tbase + r) * 128 + q * 16
            : reinterpret_cast<const unsigned char*>(g_xh)
              + (size_t)(tbase + r) * 128 + (q - 8) * 16;
        cp16(abase + r * ROWB + q * 16, src);
    }
    asm volatile("cp.async.commit_group;" ::: "memory");
}

__global__ __launch_bounds__(256, 2)
void gemm_mma_kernel(const float* __restrict__ b,
                     float*       __restrict__ out,
                     int N, int tile_lo, int tile_hi)
{
    const uint32_t sb = smem_u32(g_sm);
    const int tid  = threadIdx.x;
    const int wid  = tid >> 5;
    const int lane = tid & 31;

    #pragma unroll
    for (int j = 0; j < 4; j++) {
        const int c = tid + 256 * j;
        const int o = c >> 4;
        const int q = c & 15;
        cp16(sb + SM_WHI + o * ROWB + q * 16, g_wh + (size_t)o * 256 + q * 16);
    }
    asm volatile("cp.async.commit_group;" ::: "memory");

    int t0 = tile_lo + blockIdx.x;
    if (t0 < tile_hi) stage_tile(sb, 0, t0 * TB, tid);

    const int wm = wid >> 1;
    const int wn = wid & 1;

    const uint32_t a_off = (uint32_t)(wm * 32 + (lane & 15)) * ROWB
                           + (uint32_t)(lane >> 4) * 16;
    const int brow = wn * 32 + ((lane >> 4) << 3) + (lane & 7);
    const uint32_t b_base = sb + SM_WHI
        + (uint32_t)brow * ROWB + (uint32_t)((lane >> 3) & 1) * 16;

    const int g   = lane >> 2;
    const int tig = lane & 3;
    float2 bb[4];
    #pragma unroll
    for (int ns = 0; ns < 4; ns++) {
        int col = wn * 32 + ns * 8 + 2 * tig;
        bb[ns] = make_float2(__ldg(b + col), __ldg(b + col + 1));
    }

    int i = 0;
    for (int t = t0; t < tile_hi; t += GRIDC, i++) {
        const int nxt = t + GRIDC;
        if (nxt < tile_hi) {
            stage_tile(sb, (i + 1) & 1, nxt * TB, tid);
            asm volatile("cp.async.wait_group 1;" ::: "memory");
        } else {
            asm volatile("cp.async.wait_group 0;" ::: "memory");
        }
        __syncthreads();

        const uint32_t a_base = sb + ((i & 1) ? SM_A1 : SM_A0) + a_off;

        float acc[2][4][4];
        #pragma unroll
        for (int ms = 0; ms < 2; ms++)
            #pragma unroll
            for (int ns = 0; ns < 4; ns++)
                #pragma unroll
                for (int q = 0; q < 4; q++) acc[ms][ns][q] = 0.f;

        #pragma unroll
        for (int ks = 0; ks < 8; ks++) {
            const uint32_t ao = a_base + ks * 32;
            const uint32_t bo = b_base + ks * 32;
            uint4 ah0, ah1, bh0, bh1;
            ldm_x4(ah0, ao);
            ldm_x4(ah1, ao + 16 * ROWB);
            ldm_x4(bh0, bo);
            ldm_x4(bh1, bo + 16 * ROWB);

            mma16816h(acc[0][0], ah0, bh0.x, bh0.y);
            mma16816h(acc[0][1], ah0, bh0.z, bh0.w);
            mma16816h(acc[0][2], ah0, bh1.x, bh1.y);
            mma16816h(acc[0][3], ah0, bh1.z, bh1.w);
            mma16816h(acc[1][0], ah1, bh0.x, bh0.y);
            mma16816h(acc[1][1], ah1, bh0.z, bh0.w);
            mma16816h(acc[1][2], ah1, bh1.x, bh1.y);
            mma16816h(acc[1][3], ah1, bh1.z, bh1.w);
        }

        #pragma unroll
        for (int ms = 0; ms < 2; ms++) {
            const int node0 = t * TB + wm * 32 + ms * 16 + g;
            const int node1 = node0 + 8;
            #pragma unroll
            for (int ns = 0; ns < 4; ns++) {
                const int col = wn * 32 + ns * 8 + 2 * tig;
                if (node0 < N)
                    *reinterpret_cast<float2*>(out + (size_t)node0 * D_OUT + col) =
                        make_float2(acc[ms][ns][0] + bb[ns].x,
                                    acc[ms][ns][1] + bb[ns].y);
                if (node1 < N)
                    *reinterpret_cast<float2*>(out + (size_t)node1 * D_OUT + col) =
                        make_float2(acc[ms][ns][2] + bb[ns].x,
                                    acc[ms][ns][3] + bb[ns].y);
            }
        }
        __syncthreads();
    }
}

// ======================= launch =======================
extern "C" void kernel_launch(void* const* d_in, const int* in_sizes, int n_in,
                              void* d_out, int out_size)
{
    const float* x      = (const float*)d_in[0];
    const int*   row    = (const int*)  d_in[1];
    const int*   colptr = (const int*)  d_in[2];
    const float* W      = (const float*)d_in[3];
    const float* b      = (const float*)d_in[4];
    float*       out    = (float*)d_out;

    const int N = in_sizes[2] - 1;   // 100000
    const int ntiles = (N + TB - 1) / TB;

    // one-time host-side setup (first call is eager/non-capturing)
    static cudaStream_t s1 = nullptr;
    static cudaEvent_t  eg[4];
    static cudaEvent_t  edone;
    if (!s1) {
        cudaStreamCreateWithFlags(&s1, cudaStreamNonBlocking);
        for (int c = 0; c < 4; c++)
            cudaEventCreateWithFlags(&eg[c], cudaEventDisableTiming);
        cudaEventCreateWithFlags(&edone, cudaEventDisableTiming);
        cudaFuncSetAttribute(gemm_mma_kernel,
                             cudaFuncAttributeMaxDynamicSharedMemorySize, SM_TOT);
    }

    const int nx = N * 16;
    convert_kernel<<<XCBLK + 4, 256>>>(
        reinterpret_cast<const float4*>(x),
        reinterpret_cast<const float4*>(W), nx);

    for (int c = 0; c < 4; c++) {
        const int n_lo = c * NCHUNK;
        const int n_hi = min(n_lo + NCHUNK, N);
        if (n_lo >= N) break;
        const int gblocks = ((n_hi - n_lo) * 8 + 255) / 256;
        gather_kernel<<<gblocks, 256>>>(row, colptr, n_lo, n_hi);
        cudaEventRecord(eg[c], 0);
        cudaStreamWaitEvent(s1, eg[c], 0);

        const int t_lo = c * TCHUNK;
        const int t_hi = min(t_lo + TCHUNK, ntiles);
        gemm_mma_kernel<<<GRIDC, 256, SM_TOT, s1>>>(b, out, N, t_lo, t_hi);
    }
    cudaEventRecord(edone, s1);
    cudaStreamWaitEvent(0, edone, 0);
}